// round 14
// baseline (speedup 1.0000x reference)
#include <cuda_runtime.h>
#include <cstdint>

#define KIDS 64
#define NCANDS 16
#define BTHR 256                 // threads per block; 1 block per id
#define SENTI 0x7FFFFFFF

// Single packed accumulator: bits[0:7)=arrive count, [7:13)=valid count,
// [13:64)=sum of per-instance losses in 2^30 fixed point (exact int adds =>
// deterministic across replays regardless of arrival order).
__device__ unsigned long long g_acc = 0ULL;   // reset by the winner each launch

// ---------------- compile-time threefry (host constexpr mirror) ----------------
constexpr uint32_t crotl(uint32_t v, int d) { return (v << d) | (v >> (32 - d)); }
constexpr unsigned long long ctf(uint32_t k0, uint32_t k1,
                                 uint32_t x0, uint32_t x1) {
    uint32_t k2 = k0 ^ k1 ^ 0x1BD11BDAu;
    x0 += k0; x1 += k1;
#define CR_(r) { x0 += x1; x1 = crotl(x1, (r)); x1 ^= x0; }
    CR_(13) CR_(15) CR_(26) CR_(6)   x0 += k1; x1 += k2 + 1u;
    CR_(17) CR_(29) CR_(16) CR_(24)  x0 += k2; x1 += k0 + 2u;
    CR_(13) CR_(15) CR_(26) CR_(6)   x0 += k0; x1 += k1 + 3u;
    CR_(17) CR_(29) CR_(16) CR_(24)  x0 += k1; x1 += k2 + 4u;
    CR_(13) CR_(15) CR_(26) CR_(6)   x0 += k2; x1 += k0 + 5u;
#undef CR_
    return ((unsigned long long)x0 << 32) | x1;
}
// child key of split(key(1)) — fully input-independent
constexpr unsigned long long KKC = ctf(0u, 1u, 0u, 1u);
#define KK0 ((uint32_t)(KKC >> 32))
#define KK1 ((uint32_t)KKC)

// ---------------- runtime threefry (device, bit-exact) ----------------
__device__ __forceinline__ uint32_t rotl32(uint32_t v, int d) {
    return __funnelshift_l(v, v, d);
}
__device__ __forceinline__ void tf2x32(uint32_t k0, uint32_t k1,
                                       uint32_t x0, uint32_t x1,
                                       uint32_t& o0, uint32_t& o1) {
    uint32_t k2 = k0 ^ k1 ^ 0x1BD11BDAu;
    x0 += k0; x1 += k1;
#define R_(r) { x0 += x1; x1 = rotl32(x1, (r)); x1 ^= x0; }
    R_(13) R_(15) R_(26) R_(6)   x0 += k1; x1 += k2 + 1u;
    R_(17) R_(29) R_(16) R_(24)  x0 += k2; x1 += k0 + 2u;
    R_(13) R_(15) R_(26) R_(6)   x0 += k0; x1 += k1 + 3u;
    R_(17) R_(29) R_(16) R_(24)  x0 += k1; x1 += k2 + 4u;
    R_(13) R_(15) R_(26) R_(6)   x0 += k2; x1 += k0 + 5u;
#undef R_
    o0 = x0; o1 = x1;
}

__global__ void __launch_bounds__(BTHR)
per_id_kernel(const float* __restrict__ sem, const int* __restrict__ mask,
              float* __restrict__ out, int HW, int BC) {
    __shared__ int sF, sS, sNeg;
    __shared__ float2 sSq[BTHR];

    int t = threadIdx.x, warp = t >> 5, lane = t & 31;
    int k = blockIdx.x;              // this block owns id k

    if (t == 0) { sF = SENTI; sS = SENTI; }

    // ---- batch 0 of the scan: issued first, no dependencies ----
    int base = 0;
    int p = t * 4;
    int4 v = make_int4(-1, -1, -1, -1);
    if (p + 3 < HW) v = *reinterpret_cast<const int4*>(mask + p);
    else {
        if (p     < HW) v.x = mask[p];
        if (p + 1 < HW) v.y = mask[p + 1];
        if (p + 2 < HW) v.z = mask[p + 2];
    }

    // ---- candidates (warp 0): one runtime threefry, overlapped with loads ----
    int cand = 0, candval = 0;
    if (warp == 0 && lane < NCANDS) {
        uint32_t o0, o1;
        tf2x32(KK0, KK1, 0u, (uint32_t)(k * NCANDS + lane), o0, o1);
        cand = (int)((o0 ^ o1) % (uint32_t)HW);
        candval = __ldg(mask + cand);            // in flight...
    }

    // orders sF/sS init before any atomic below (single upfront barrier)
    __syncthreads();

    // warp 0 resolves the negative (stalls on candval; other warps scan ahead)
    if (warp == 0) {
        bool ok = (lane < NCANDS) && (candval != k);
        unsigned bal = __ballot_sync(0xffffffffu, ok) & 0xFFFFu;
        int neg = __shfl_sync(0xffffffffu, cand, bal ? (__ffs(bal) - 1) : 0);
        if (lane == 0) sNeg = neg;
    }

    // ---- block scan: two smallest positions of id k (1 barrier / batch) ----
    while (true) {
        // per-thread two-min over its 4 pixels
        unsigned m = (v.x == k ? 1u : 0u) | (v.y == k ? 2u : 0u) |
                     (v.z == k ? 4u : 0u) | (v.w == k ? 8u : 0u);
        if (m) {
            int fl = base + t * 4 + (__ffs(m) - 1);
            unsigned mr = m & (m - 1);
            int sl = mr ? (base + t * 4 + (__ffs(mr) - 1)) : SENTI;
            // displaced-value two-min merge (read filters are monotonic-safe)
            int cnd;
            if (fl < sF) {
                int prev = atomicMin(&sF, fl);
                cnd = (prev == SENTI) ? SENTI : max(fl, prev);
            } else {
                cnd = fl;
            }
            if (cnd < sS) atomicMin(&sS, cnd);
            if (sl != SENTI && sl < sS) atomicMin(&sS, sl);
        }
        __syncthreads();
        if (sS != SENTI || base + BTHR * 4 >= HW) break;   // exact fallback loops
        base += BTHR * 4;
        p = base + t * 4;
        v = make_int4(-1, -1, -1, -1);
        if (p + 3 < HW) v = *reinterpret_cast<const int4*>(mask + p);
        else {
            if (p     < HW) v.x = mask[p];
            if (p + 1 < HW) v.y = mask[p + 1];
            if (p + 2 < HW) v.z = mask[p + 2];
        }
    }

    bool valid = (sS != SENTI) && (k != 0);
    int fi = min(sF, HW - 1);
    int si = min(sS, HW - 1);
    int neg = sNeg;                  // ordered by the scan barrier

    // ---- finalize: channel-parallel gathers (threads c < BC active) ----
    float dap = 0.f, dan = 0.f;
    for (int c = t; c < BC; c += BTHR) {
        size_t off = (size_t)c * (size_t)HW;
        float a  = __ldg(sem + off + fi);
        float pv = __ldg(sem + off + si);
        float n  = __ldg(sem + off + neg);
        float e1 = a - pv + 1e-6f;
        float e2 = a - n  + 1e-6f;
        dap = fmaf(e1, e1, dap);
        dan = fmaf(e2, e2, dan);
    }
    sSq[t] = make_float2(dap, dan);
    __syncthreads();

    // warp 0: deterministic fixed-order reduction, then the packed atomic.
    // Only warps whose threads can hold channels contribute nonzero partials.
    if (warp == 0) {
        const int NW = (BTHR < 32 * ((BTHR + 31) / 32)) ? BTHR / 32 : BTHR / 32;
        float ta = 0.f, tn = 0.f;
        #pragma unroll
        for (int i = 0; i < BTHR / 32; i++) {
            if (i * 32 < 128 || i * 32 < BTHR) {     // keep full coverage; cheap
                float2 q = sSq[lane + i * 32];
                ta += q.x; tn += q.y;
            }
        }
        (void)NW;
        #pragma unroll
        for (int o = 16; o; o >>= 1) {
            ta += __shfl_down_sync(0xffffffffu, ta, o);
            tn += __shfl_down_sync(0xffffffffu, tn, o);
        }
        if (lane == 0) {
            float per = fmaxf(sqrtf(ta) - sqrtf(tn) + 1.0f, 0.0f);
            unsigned long long fx = valid
                ? (unsigned long long)((double)per * 1073741824.0 + 0.5) : 0ULL;
            unsigned long long add = (fx << 13) |
                                     (valid ? (1ULL << 7) : 0ULL) | 1ULL;
            unsigned long long old = atomicAdd(&g_acc, add);
            if ((old & 0x7FULL) == (unsigned long long)(KIDS - 1)) {
                unsigned long long full = old + add;
                unsigned cnt = (unsigned)((full >> 7) & 0x3FULL);
                double tot = (double)(full >> 13) * (1.0 / 1073741824.0);
                out[0] = (cnt > 0) ? (float)(tot / (double)cnt) : 0.0f;
                g_acc = 0ULL;        // reset for the next graph replay
            }
        }
    }
}

extern "C" void kernel_launch(void* const* d_in, const int* in_sizes, int n_in,
                              void* d_out, int out_size) {
    const float* sem  = (const float*)d_in[0];
    const int*   mask = (const int*)d_in[1];
    float*       out  = (float*)d_out;
    int HW = in_sizes[1];
    int BC = in_sizes[0] / HW;

    per_id_kernel<<<KIDS, BTHR>>>(sem, mask, out, HW, BC);
}

// round 15
// speedup vs baseline: 1.0504x; 1.0504x over previous
#include <cuda_runtime.h>
#include <cstdint>

#define KIDS 64
#define NCANDS 16
#define BTHR 256                 // threads per block; 1 block per id
#define SENTI 0x7FFFFFFF

// Single packed accumulator: bits[0:7)=arrive count, [7:13)=valid count,
// [13:64)=sum of per-instance losses in 2^30 fixed point (exact int adds =>
// deterministic across replays regardless of arrival order).
__device__ unsigned long long g_acc = 0ULL;   // reset by the winner each launch

// ---------------- compile-time threefry (host constexpr mirror) ----------------
constexpr uint32_t crotl(uint32_t v, int d) { return (v << d) | (v >> (32 - d)); }
constexpr unsigned long long ctf(uint32_t k0, uint32_t k1,
                                 uint32_t x0, uint32_t x1) {
    uint32_t k2 = k0 ^ k1 ^ 0x1BD11BDAu;
    x0 += k0; x1 += k1;
#define CR_(r) { x0 += x1; x1 = crotl(x1, (r)); x1 ^= x0; }
    CR_(13) CR_(15) CR_(26) CR_(6)   x0 += k1; x1 += k2 + 1u;
    CR_(17) CR_(29) CR_(16) CR_(24)  x0 += k2; x1 += k0 + 2u;
    CR_(13) CR_(15) CR_(26) CR_(6)   x0 += k0; x1 += k1 + 3u;
    CR_(17) CR_(29) CR_(16) CR_(24)  x0 += k1; x1 += k2 + 4u;
    CR_(13) CR_(15) CR_(26) CR_(6)   x0 += k2; x1 += k0 + 5u;
#undef CR_
    return ((unsigned long long)x0 << 32) | x1;
}
// child key of split(key(1)) — fully input-independent
constexpr unsigned long long KKC = ctf(0u, 1u, 0u, 1u);
#define KK0 ((uint32_t)(KKC >> 32))
#define KK1 ((uint32_t)KKC)

// ---------------- runtime threefry (device, bit-exact) ----------------
__device__ __forceinline__ uint32_t rotl32(uint32_t v, int d) {
    return __funnelshift_l(v, v, d);
}
__device__ __forceinline__ void tf2x32(uint32_t k0, uint32_t k1,
                                       uint32_t x0, uint32_t x1,
                                       uint32_t& o0, uint32_t& o1) {
    uint32_t k2 = k0 ^ k1 ^ 0x1BD11BDAu;
    x0 += k0; x1 += k1;
#define R_(r) { x0 += x1; x1 = rotl32(x1, (r)); x1 ^= x0; }
    R_(13) R_(15) R_(26) R_(6)   x0 += k1; x1 += k2 + 1u;
    R_(17) R_(29) R_(16) R_(24)  x0 += k2; x1 += k0 + 2u;
    R_(13) R_(15) R_(26) R_(6)   x0 += k0; x1 += k1 + 3u;
    R_(17) R_(29) R_(16) R_(24)  x0 += k1; x1 += k2 + 4u;
    R_(13) R_(15) R_(26) R_(6)   x0 += k2; x1 += k0 + 5u;
#undef R_
    o0 = x0; o1 = x1;
}

__global__ void __launch_bounds__(BTHR)
per_id_kernel(const float* __restrict__ sem, const int* __restrict__ mask,
              float* __restrict__ out, int HW, int BC) {
    __shared__ int sF, sS;

    int t = threadIdx.x, warp = t >> 5, lane = t & 31;
    int k = blockIdx.x;              // this block owns id k

    if (t == 0) { sF = SENTI; sS = SENTI; }

    // ---- batch 0 of the scan: issued first, no dependencies ----
    int base = 0;
    int p = t * 4;
    int4 v = make_int4(-1, -1, -1, -1);
    if (p + 3 < HW) v = *reinterpret_cast<const int4*>(mask + p);
    else {
        if (p     < HW) v.x = mask[p];
        if (p + 1 < HW) v.y = mask[p + 1];
        if (p + 2 < HW) v.z = mask[p + 2];
    }

    // ---- candidates (warp 0): one runtime threefry, overlapped with loads ----
    int cand = 0, candval = 0;
    if (warp == 0 && lane < NCANDS) {
        uint32_t o0, o1;
        tf2x32(KK0, KK1, 0u, (uint32_t)(k * NCANDS + lane), o0, o1);
        cand = (int)((o0 ^ o1) % (uint32_t)HW);
        candval = __ldg(mask + cand);            // in flight...
    }

    // orders sF/sS init before any atomic below (single upfront barrier)
    __syncthreads();

    // warp 0 resolves the negative (stalls on candval; other warps scan ahead);
    // neg stays warp-0-register-resident — never touches smem.
    int neg = 0;
    if (warp == 0) {
        bool ok = (lane < NCANDS) && (candval != k);
        unsigned bal = __ballot_sync(0xffffffffu, ok) & 0xFFFFu;
        neg = __shfl_sync(0xffffffffu, cand, bal ? (__ffs(bal) - 1) : 0);
    }

    // ---- block scan: two smallest positions of id k (1 barrier / batch) ----
    while (true) {
        unsigned m = (v.x == k ? 1u : 0u) | (v.y == k ? 2u : 0u) |
                     (v.z == k ? 4u : 0u) | (v.w == k ? 8u : 0u);
        if (m) {
            int fl = base + t * 4 + (__ffs(m) - 1);
            unsigned mr = m & (m - 1);
            int sl = mr ? (base + t * 4 + (__ffs(mr) - 1)) : SENTI;
            // displaced-value two-min merge (read filters are monotonic-safe)
            int cnd;
            if (fl < sF) {
                int prev = atomicMin(&sF, fl);
                cnd = (prev == SENTI) ? SENTI : max(fl, prev);
            } else {
                cnd = fl;
            }
            if (cnd < sS) atomicMin(&sS, cnd);
            if (sl != SENTI && sl < sS) atomicMin(&sS, sl);
        }
        __syncthreads();
        if (sS != SENTI || base + BTHR * 4 >= HW) break;   // exact fallback loops
        base += BTHR * 4;
        p = base + t * 4;
        v = make_int4(-1, -1, -1, -1);
        if (p + 3 < HW) v = *reinterpret_cast<const int4*>(mask + p);
        else {
            if (p     < HW) v.x = mask[p];
            if (p + 1 < HW) v.y = mask[p + 1];
            if (p + 2 < HW) v.z = mask[p + 2];
        }
    }

    // ---- finalize: warp 0 alone — gathers + in-warp reduce + atomic ----
    // (no smem round-trip, no extra barrier; warps 1..7 simply exit)
    if (warp != 0) return;

    bool valid = (sS != SENTI) && (k != 0);
    int fi = min(sF, HW - 1);
    int si = min(sS, HW - 1);

    float dap = 0.f, dan = 0.f;
    #pragma unroll
    for (int i = 0; i < 4; i++) {                // covers BC <= 128 (BC = 76)
        int c = lane + i * 32;
        if (c < BC) {
            size_t off = (size_t)c * (size_t)HW;
            float a  = __ldg(sem + off + fi);
            float pv = __ldg(sem + off + si);
            float n  = __ldg(sem + off + neg);
            float e1 = a - pv + 1e-6f;
            float e2 = a - n  + 1e-6f;
            dap = fmaf(e1, e1, dap);
            dan = fmaf(e2, e2, dan);
        }
    }
    for (int c = lane + 128; c < BC; c += 32) {  // generic tail (unused here)
        size_t off = (size_t)c * (size_t)HW;
        float a  = __ldg(sem + off + fi);
        float pv = __ldg(sem + off + si);
        float n  = __ldg(sem + off + neg);
        float e1 = a - pv + 1e-6f;
        float e2 = a - n  + 1e-6f;
        dap = fmaf(e1, e1, dap);
        dan = fmaf(e2, e2, dan);
    }
    #pragma unroll
    for (int o = 16; o; o >>= 1) {
        dap += __shfl_down_sync(0xffffffffu, dap, o);
        dan += __shfl_down_sync(0xffffffffu, dan, o);
    }
    if (lane == 0) {
        float per = fmaxf(sqrtf(dap) - sqrtf(dan) + 1.0f, 0.0f);
        unsigned long long fx = valid
            ? (unsigned long long)((double)per * 1073741824.0 + 0.5) : 0ULL;
        unsigned long long add = (fx << 13) |
                                 (valid ? (1ULL << 7) : 0ULL) | 1ULL;
        unsigned long long old = atomicAdd(&g_acc, add);
        if ((old & 0x7FULL) == (unsigned long long)(KIDS - 1)) {
            unsigned long long full = old + add;   // exact packed total
            unsigned cnt = (unsigned)((full >> 7) & 0x3FULL);
            double tot = (double)(full >> 13) * (1.0 / 1073741824.0);
            out[0] = (cnt > 0) ? (float)(tot / (double)cnt) : 0.0f;
            g_acc = 0ULL;            // reset for the next graph replay
        }
    }
}

extern "C" void kernel_launch(void* const* d_in, const int* in_sizes, int n_in,
                              void* d_out, int out_size) {
    const float* sem  = (const float*)d_in[0];
    const int*   mask = (const int*)d_in[1];
    float*       out  = (float*)d_out;
    int HW = in_sizes[1];
    int BC = in_sizes[0] / HW;

    per_id_kernel<<<KIDS, BTHR>>>(sem, mask, out, HW, BC);
}